// round 10
// baseline (speedup 1.0000x reference)
#include <cuda_runtime.h>
#include <cuda_bf16.h>

#define SS 7
#define NCH 25
#define MAXCELLS 8192
#define LAMBDA_COORD 5.0f
#define LAMBDA_NOOBJ 0.5f
#define EPS_SQRT 1e-6f
#define EPS_IOU 1e-10f
#define TPB 256
#define NWARP (TPB / 32)
#define MAXBLK 64
#define CPB 256                  // cells per block (== TPB)

// __device__ globals (zero-init; kernel self-resets -> identical on every replay)
__device__ double g_part [MAXBLK];
__device__ double g_part2[MAXBLK];
__device__ int    g_cnt   = 0;
__device__ int    g_done1 = 0;
__device__ int    g_done2 = 0;
// compacted per-object-cell data: target corners+area, pred corners+area+conf
__device__ float  g_tx1[MAXCELLS], g_ty1[MAXCELLS], g_tx2[MAXCELLS], g_ty2[MAXCELLS], g_ta[MAXCELLS];
__device__ float  g_px1[MAXCELLS], g_py1[MAXCELLS], g_px2[MAXCELLS], g_py2[MAXCELLS], g_pa[MAXCELLS], g_pc[MAXCELLS];

__global__ void __launch_bounds__(TPB)
k_yolo_coal(const float* __restrict__ pred,
            const float* __restrict__ targ,
            float* __restrict__ out,
            int M, int nblocks, float invB) {
    const int tid  = threadIdx.x;
    const int lane = tid & 31;
    const int wid  = tid >> 5;

    const int cell0  = blockIdx.x * CPB;
    const int ncells = min(CPB, M - cell0);          // 256 (last block: 128)
    const int nelem  = ncells * NCH;                 // slice elements
    const int nf4    = nelem >> 2;                   // ncells*25 divisible by 4 here

    __shared__ float  s_targ[CPB * NCH];             // 25.6 KB staged targ slice
    __shared__ int    s_wbase[NWARP];
    __shared__ int    s_cnt, s_gbase;
    __shared__ double swred[NWARP];
    if (tid == 0) s_cnt = 0;

    // ---- Stage targ slice: coalesced float4 (slice base 100*CPB*bid is 16B-aligned)
    {
        const float4* t4p = (const float4*)(targ + (size_t)cell0 * NCH);
        float4* s4 = (float4*)s_targ;
        for (int f = tid; f < nf4; f += TPB) s4[f] = t4p[f];
    }
    __syncthreads();

    // ---- Obj compaction: thread-per-cell, targ box from smem --------------
    double local = 0.0;
    bool isObj = false;
    if (tid < ncells) {
        float t4 = s_targ[tid * NCH + 4];
        isObj = (t4 > 0.0f);
    }
    unsigned m = __ballot_sync(0xffffffffu, isObj);
    int nobj = __popc(m);
    if (lane == 0) s_wbase[wid] = (nobj > 0) ? atomicAdd(&s_cnt, nobj) : 0;
    __syncthreads();
    if (tid == 0) s_gbase = (s_cnt > 0) ? atomicAdd(&g_cnt, s_cnt) : 0;
    __syncthreads();
    if (isObj) {
        int pos = s_gbase + s_wbase[wid] + __popc(m & ((1u << lane) - 1));
        // targ box from smem
        const float* tt = s_targ + tid * NCH;
        float cx = tt[0], cy = tt[1], w = tt[2], h = tt[3];
        float x1 = cx - w*0.5f, y1 = cy - h*0.5f;
        float x2 = cx + w*0.5f, y2 = cy + h*0.5f;
        g_tx1[pos]=x1; g_ty1[pos]=y1; g_tx2[pos]=x2; g_ty2[pos]=y2;
        g_ta [pos]=(x2-x1)*(y2-y1);
        // pred box: 5 scalar loads, only ~4% of threads
        const float* pp = pred + (size_t)(cell0 + tid) * NCH;
        float pcx = pp[0], pcy = pp[1], pw = pp[2], ph = pp[3], pconf = pp[4];
        float a1 = pcx - pw*0.5f, b1 = pcy - ph*0.5f;
        float a2 = pcx + pw*0.5f, b2 = pcy + ph*0.5f;
        g_px1[pos]=a1; g_py1[pos]=b1; g_px2[pos]=a2; g_py2[pos]=b2;
        g_pa [pos]=(a2-a1)*(b2-b1);
        g_pc [pos]=pconf;
    }

    // ---- Elementwise sweep over pred: coalesced float4, channel decoded ----
    {
        const float4* p4p = (const float4*)(pred + (size_t)cell0 * NCH);
        for (int f = tid; f < nf4; f += TPB) {
            float4 pv4 = p4p[f];
            float pvv[4] = {pv4.x, pv4.y, pv4.z, pv4.w};
            int le0 = f << 2;
            float acc = 0.0f;
            #pragma unroll
            for (int k = 0; k < 4; k++) {
                int le = le0 + k;
                int lcell = le / NCH;
                int ch    = le - lcell * NCH;
                float p  = pvv[k];
                float t  = s_targ[le];
                float t4 = s_targ[lcell * NCH + 4];
                bool obj = (t4 > 0.0f);
                float v;
                if (ch < 2) {
                    float d = p - t;
                    v = obj ? LAMBDA_COORD * d * d : 0.0f;
                } else if (ch < 4) {
                    float d = sqrtf(p + EPS_SQRT) - sqrtf(t + EPS_SQRT);
                    v = obj ? LAMBDA_COORD * d * d : 0.0f;
                } else if (ch == 4) {
                    v = obj ? 0.0f : LAMBDA_NOOBJ * p * p;   // obj conf in phase 2
                } else {
                    float d = p - t;
                    v = obj ? d * d : 0.0f;
                }
                acc += v;
            }
            local += (double)acc;
        }
    }

    // ---- block reduce phase-1 losses ---------------------------------------
    #pragma unroll
    for (int off = 16; off > 0; off >>= 1)
        local += __shfl_down_sync(0xffffffffu, local, off);
    if (lane == 0) swred[wid] = local;
    __syncthreads();
    if (wid == 0) {
        double v = (lane < NWARP) ? swred[lane] : 0.0;
        #pragma unroll
        for (int off = NWARP >> 1; off > 0; off >>= 1)
            v += __shfl_down_sync(0xffffffffu, v, off);
        if (lane == 0) g_part[blockIdx.x] = v;
    }

    // ---- Grid barrier (25 blocks, all co-resident) -------------------------
    __threadfence();
    __syncthreads();
    if (tid == 0) atomicAdd(&g_done1, 1);
    if (tid == 0) {
        volatile int* vd = &g_done1;
        while (*vd < nblocks) { }
    }
    __syncthreads();
    __threadfence();

    const int K = g_cnt;

    // ---- Phase 2: warp-per-object-cell conf loss ---------------------------
    double l2 = 0.0;
    const int gwarp  = blockIdx.x * NWARP + wid;
    const int nwarps = nblocks * NWARP;
    for (int c = gwarp; c < K; c += nwarps) {
        float bx1 = g_px1[c], by1 = g_py1[c], bx2 = g_px2[c], by2 = g_py2[c];
        float ba  = g_pa[c],  bpc = g_pc[c];
        float best = -1.0f;
        for (int j = lane; j < K; j += 32) {
            float iw = fminf(bx2, g_tx2[j]) - fmaxf(bx1, g_tx1[j]);
            float ih = fminf(by2, g_ty2[j]) - fmaxf(by1, g_ty1[j]);
            iw = fmaxf(iw, 0.0f);
            ih = fmaxf(ih, 0.0f);
            float inter = iw * ih;
            float iou = __fdividef(inter, ba + g_ta[j] - inter + EPS_IOU);
            best = fmaxf(best, iou);
        }
        #pragma unroll
        for (int off = 16; off > 0; off >>= 1)
            best = fmaxf(best, __shfl_xor_sync(0xffffffffu, best, off));
        if (lane == 0) {
            float d = bpc - best;
            l2 += (double)(d * d);
        }
    }

    // ---- block reduce phase-2 losses ---------------------------------------
    if (lane == 0) swred[wid] = l2;
    __syncthreads();
    if (wid == 0) {
        double v = (lane < NWARP) ? swred[lane] : 0.0;
        #pragma unroll
        for (int off = NWARP >> 1; off > 0; off >>= 1)
            v += __shfl_down_sync(0xffffffffu, v, off);
        if (lane == 0) g_part2[blockIdx.x] = v;
    }

    // ---- Last block finalizes + resets -------------------------------------
    __threadfence();
    __syncthreads();
    __shared__ int is_last;
    if (tid == 0) is_last = (atomicAdd(&g_done2, 1) == nblocks - 1) ? 1 : 0;
    __syncthreads();
    if (!is_last) return;

    if (tid == 0) {
        double tot = 0.0;
        for (int b = 0; b < nblocks; b++) tot += g_part[b] + g_part2[b];
        out[0] = (float)(tot * (double)invB);
        g_cnt   = 0;   // reset for next graph replay
        g_done1 = 0;
        g_done2 = 0;
    }
}

extern "C" void kernel_launch(void* const* d_in, const int* in_sizes, int n_in,
                              void* d_out, int out_size) {
    const float* pred = (const float*)d_in[0];
    const float* targ = (const float*)d_in[1];
    float* out = (float*)d_out;

    int total = in_sizes[0];           // B * S * S * N
    int M = total / NCH;               // 6272 cells
    int B = M / (SS * SS);
    float invB = 1.0f / (float)B;

    int nblocks = (M + CPB - 1) / CPB; // 25 (co-resident: 25 << #SMs)
    k_yolo_coal<<<nblocks, TPB>>>(pred, targ, out, M, nblocks, invB);
}

// round 13
// speedup vs baseline: 1.1687x; 1.1687x over previous
#include <cuda_runtime.h>
#include <cuda_bf16.h>

#define SS 7
#define NCH 25
#define MAXCELLS 8192
#define LAMBDA_COORD 5.0f
#define LAMBDA_NOOBJ 0.5f
#define EPS_SQRT 1e-6f
#define EPS_IOU 1e-10f
#define TPB 512
#define NWARP (TPB / 32)
#define MAXBLK 64
#define CPB 448                    // cells per block; 14 * 448 = 6272 exactly

// __device__ globals (zero-init; kernel self-resets -> identical on every replay)
__device__ double g_part [MAXBLK];
__device__ double g_part2[MAXBLK];
__device__ int    g_cnt   = 0;
__device__ int    g_done1 = 0;
__device__ int    g_done2 = 0;
// compacted per-object-cell data
__device__ float  g_tx1[MAXCELLS], g_ty1[MAXCELLS], g_tx2[MAXCELLS], g_ty2[MAXCELLS], g_ta[MAXCELLS];
__device__ float  g_px1[MAXCELLS], g_py1[MAXCELLS], g_px2[MAXCELLS], g_py2[MAXCELLS], g_pa[MAXCELLS], g_pc[MAXCELLS];

__global__ void __launch_bounds__(TPB)
k_yolo_hyb(const float* __restrict__ pred,
           const float* __restrict__ targ,
           float* __restrict__ out,
           int M, int nblocks, float invB) {
    __shared__ float  s_targ[CPB * NCH];       // 44.8 KB static
    __shared__ float  s_conf[CPB];
    __shared__ int    s_wbase[NWARP];
    __shared__ int    s_cnt, s_gbase;
    __shared__ double swred[NWARP];

    const int tid  = threadIdx.x;
    const int lane = tid & 31;
    const int wid  = tid >> 5;

    const int cell0  = blockIdx.x * CPB;
    const int ncells = min(CPB, M - cell0);
    const int nf4    = (ncells * NCH) >> 2;    // 448*25/4 = 2800

    if (tid == 0) s_cnt = 0;

    // ---- Stage targ slice coalesced (float4; base 44800*bid is 16B-aligned)
    {
        const float4* t4p = (const float4*)(targ + (size_t)cell0 * NCH);
        float4* s4 = (float4*)s_targ;
        #pragma unroll 2
        for (int f = tid; f < nf4; f += TPB) s4[f] = t4p[f];
    }
    __syncthreads();

    // ---- Extract per-cell conf (stride-25 LDS: conflict-free, 25 coprime 32)
    bool isObj = false;
    if (tid < ncells) {
        float t4 = s_targ[tid * NCH + 4];
        s_conf[tid] = t4;
        isObj = (t4 > 0.0f);
    }

    // ---- Obj compaction: targ box from smem, pred box 5 scalar LDG (rare) --
    unsigned m = __ballot_sync(0xffffffffu, isObj);
    int nobj = __popc(m);
    if (lane == 0) s_wbase[wid] = (nobj > 0) ? atomicAdd(&s_cnt, nobj) : 0;
    __syncthreads();
    if (tid == 0) s_gbase = (s_cnt > 0) ? atomicAdd(&g_cnt, s_cnt) : 0;
    __syncthreads();
    if (isObj) {
        int pos = s_gbase + s_wbase[wid] + __popc(m & ((1u << lane) - 1));
        const float* tt = s_targ + tid * NCH;
        float cx = tt[0], cy = tt[1], w = tt[2], h = tt[3];
        float x1 = cx - w*0.5f, y1 = cy - h*0.5f;
        float x2 = cx + w*0.5f, y2 = cy + h*0.5f;
        g_tx1[pos]=x1; g_ty1[pos]=y1; g_tx2[pos]=x2; g_ty2[pos]=y2;
        g_ta [pos]=(x2-x1)*(y2-y1);
        const float* pp = pred + (size_t)(cell0 + tid) * NCH;
        float pcx = pp[0], pcy = pp[1], pw = pp[2], ph = pp[3], pconf = pp[4];
        float a1 = pcx - pw*0.5f, b1 = pcy - ph*0.5f;
        float a2 = pcx + pw*0.5f, b2 = pcy + ph*0.5f;
        g_px1[pos]=a1; g_py1[pos]=b1; g_px2[pos]=a2; g_py2[pos]=b2;
        g_pa [pos]=(a2-a1)*(b2-b1);
        g_pc [pos]=pconf;
    }

    // ---- Elementwise sweep over pred: coalesced float4, lean decode --------
    double local = 0.0;
    {
        const float4* p4p = (const float4*)(pred + (size_t)cell0 * NCH);
        #pragma unroll 2
        for (int f = tid; f < nf4; f += TPB) {
            float4 pv4 = p4p[f];
            float pvv[4] = {pv4.x, pv4.y, pv4.z, pv4.w};
            int le0 = f << 2;
            float acc = 0.0f;
            #pragma unroll
            for (int k = 0; k < 4; k++) {
                int le = le0 + k;
                int lcell = le / NCH;            // ptxas emits magic-number div
                int ch = le - lcell * NCH;
                float p = pvv[k];
                float t = s_targ[le];
                float o = (s_conf[lcell] > 0.0f) ? 1.0f : 0.0f;
                bool is_wh = (ch == 2) | (ch == 3);
                float dlin = p - t;
                float dsq  = sqrtf(p + EPS_SQRT) - sqrtf(t + EPS_SQRT);
                float d = is_wh ? dsq : dlin;
                float w = (ch < 4) ? (LAMBDA_COORD * o)
                        : (ch == 4) ? (LAMBDA_NOOBJ * (1.0f - o))
                        : o;
                acc += w * d * d;
            }
            local += (double)acc;
        }
    }

    // ---- block reduce phase-1 losses ---------------------------------------
    #pragma unroll
    for (int off = 16; off > 0; off >>= 1)
        local += __shfl_down_sync(0xffffffffu, local, off);
    if (lane == 0) swred[wid] = local;
    __syncthreads();
    if (wid == 0) {
        double v = (lane < NWARP) ? swred[lane] : 0.0;
        #pragma unroll
        for (int off = 8; off > 0; off >>= 1)
            v += __shfl_down_sync(0xffffffffu, v, off);
        if (lane == 0) g_part[blockIdx.x] = v;
    }

    // ---- Grid barrier (14 blocks, all co-resident) -------------------------
    __threadfence();
    __syncthreads();
    if (tid == 0) atomicAdd(&g_done1, 1);
    if (tid == 0) {
        volatile int* vd = &g_done1;
        while (*vd < nblocks) { }
    }
    __syncthreads();
    __threadfence();

    const int K = g_cnt;

    // ---- Phase 2: warp-per-object-cell conf loss ---------------------------
    double l2 = 0.0;
    const int gwarp  = blockIdx.x * NWARP + wid;
    const int nwarps = nblocks * NWARP;
    for (int c = gwarp; c < K; c += nwarps) {
        float bx1 = g_px1[c], by1 = g_py1[c], bx2 = g_px2[c], by2 = g_py2[c];
        float ba  = g_pa[c],  bpc = g_pc[c];
        float best = -1.0f;
        for (int j = lane; j < K; j += 32) {
            float iw = fminf(bx2, g_tx2[j]) - fmaxf(bx1, g_tx1[j]);
            float ih = fminf(by2, g_ty2[j]) - fmaxf(by1, g_ty1[j]);
            iw = fmaxf(iw, 0.0f);
            ih = fmaxf(ih, 0.0f);
            float inter = iw * ih;
            float iou = __fdividef(inter, ba + g_ta[j] - inter + EPS_IOU);
            best = fmaxf(best, iou);
        }
        #pragma unroll
        for (int off = 16; off > 0; off >>= 1)
            best = fmaxf(best, __shfl_xor_sync(0xffffffffu, best, off));
        if (lane == 0) {
            float d = bpc - best;
            l2 += (double)(d * d);
        }
    }

    // ---- block reduce phase-2 losses ---------------------------------------
    if (lane == 0) swred[wid] = l2;
    __syncthreads();
    if (wid == 0) {
        double v = (lane < NWARP) ? swred[lane] : 0.0;
        #pragma unroll
        for (int off = 8; off > 0; off >>= 1)
            v += __shfl_down_sync(0xffffffffu, v, off);
        if (lane == 0) g_part2[blockIdx.x] = v;
    }

    // ---- Last block finalizes + resets -------------------------------------
    __threadfence();
    __syncthreads();
    __shared__ int is_last;
    if (tid == 0) is_last = (atomicAdd(&g_done2, 1) == nblocks - 1) ? 1 : 0;
    __syncthreads();
    if (!is_last) return;

    if (tid == 0) {
        double tot = 0.0;
        for (int b = 0; b < nblocks; b++) tot += g_part[b] + g_part2[b];
        out[0] = (float)(tot * (double)invB);
        g_cnt   = 0;   // reset for next graph replay
        g_done1 = 0;
        g_done2 = 0;
    }
}

extern "C" void kernel_launch(void* const* d_in, const int* in_sizes, int n_in,
                              void* d_out, int out_size) {
    const float* pred = (const float*)d_in[0];
    const float* targ = (const float*)d_in[1];
    float* out = (float*)d_out;

    int total = in_sizes[0];            // B * S * S * N
    int M = total / NCH;                // 6272 cells
    int B = M / (SS * SS);
    float invB = 1.0f / (float)B;

    int nblocks = (M + CPB - 1) / CPB;  // 14 (co-resident: 14 << #SMs)
    k_yolo_hyb<<<nblocks, TPB>>>(pred, targ, out, M, nblocks, invB);
}

// round 14
// speedup vs baseline: 1.4571x; 1.2468x over previous
#include <cuda_runtime.h>
#include <cuda_bf16.h>

#define SS 7
#define NCH 25
#define MAXCELLS 8192
#define LAMBDA_COORD 5.0f
#define LAMBDA_NOOBJ 0.5f
#define EPS_SQRT 1e-6f
#define EPS_IOU 1e-10f
#define TPB 512
#define NWARP (TPB / 32)
#define MAXBLK 64

// __device__ globals (zero-init; kernel self-resets -> identical on every replay)
__device__ double g_part[MAXBLK];
__device__ int    g_cnt   = 0;
__device__ int    g_done1 = 0;
__device__ int    g_done2 = 0;
// compacted object-target boxes: corners as float4 + area
__device__ float4 g_tbox[MAXCELLS];
__device__ float  g_ta [MAXCELLS];

__global__ void __launch_bounds__(TPB)
k_yolo_v14(const float* __restrict__ pred,
           const float* __restrict__ targ,
           float* __restrict__ out,
           int M, int nblocks, float invB) {
    const int tid  = threadIdx.x;
    const int lane = tid & 31;
    const int wid  = tid >> 5;
    const int i    = blockIdx.x * TPB + tid;   // owned cell

    __shared__ int   s_wbase[NWARP];
    __shared__ int   s_cnt, s_gbase;
    __shared__ float swred[NWARP];
    if (tid == 0) s_cnt = 0;
    __syncthreads();

    // ---------------- Phase 1: own-cell losses + target compaction ----------
    float local = 0.0f;
    bool isObj = false;
    float px1=0.f, py1=0.f, px2=0.f, py2=0.f, pa=0.f, pc=0.f;

    if (i < M) {
        const float* pp = pred + (size_t)i * NCH;
        const float* tt = targ + (size_t)i * NCH;
        float t4 = __ldg(&tt[4]);
        pc = __ldg(&pp[4]);
        if (t4 > 0.0f) {
            isObj = true;
            float p0 = pp[0], p1 = pp[1], p2 = pp[2], p3 = pp[3];
            float t0 = tt[0], t1 = tt[1], t2 = tt[2], t3 = tt[3];
            float dx = p0 - t0;
            float dy = p1 - t1;
            float sw = sqrtf(p2 + EPS_SQRT) - sqrtf(t2 + EPS_SQRT);
            float sh = sqrtf(p3 + EPS_SQRT) - sqrtf(t3 + EPS_SQRT);
            float cl = 0.0f;
            #pragma unroll
            for (int c = 5; c < NCH; c++) {
                float d = pp[c] - tt[c];
                cl += d * d;
            }
            local += LAMBDA_COORD * (dx*dx + dy*dy + sw*sw + sh*sh) + cl;
            // pred box stays in registers for phase 2
            px1 = p0 - p2*0.5f;  py1 = p1 - p3*0.5f;
            px2 = p0 + p2*0.5f;  py2 = p1 + p3*0.5f;
            pa  = (px2 - px1) * (py2 - py1);
            // compact target box
            float x1 = t0 - t2*0.5f, y1 = t1 - t3*0.5f;
            float x2 = t0 + t2*0.5f, y2 = t1 + t3*0.5f;
            // position via warp+block aggregation below; stash corners in regs
            px1 = px1; // (no-op, clarity)
            // store after offsets computed
            // temporarily keep in registers:
            // reuse variables by writing after pos known (below)
            // -- we need them here:
            // write deferred using x1,y1,x2,y2 captured below via lambda-free code:
            // (handled after pos computation)
            // To keep scope, save to locals:
            // use shared of nothing; just recompute cheap values after pos
            (void)x1; (void)y1; (void)x2; (void)y2;
        } else {
            local += LAMBDA_NOOBJ * pc * pc;
        }
    }

    // warp -> block -> one global atomic for compaction offsets
    unsigned m = __ballot_sync(0xffffffffu, isObj);
    int nobj = __popc(m);
    if (lane == 0) s_wbase[wid] = (nobj > 0) ? atomicAdd(&s_cnt, nobj) : 0;
    __syncthreads();
    if (tid == 0) s_gbase = (s_cnt > 0) ? atomicAdd(&g_cnt, s_cnt) : 0;
    __syncthreads();
    if (isObj) {
        int pos = s_gbase + s_wbase[wid] + __popc(m & ((1u << lane) - 1));
        const float* tt = targ + (size_t)i * NCH;
        float t0 = tt[0], t1 = tt[1], t2 = tt[2], t3 = tt[3];  // L1/L2 hot
        float x1 = t0 - t2*0.5f, y1 = t1 - t3*0.5f;
        float x2 = t0 + t2*0.5f, y2 = t1 + t3*0.5f;
        g_tbox[pos] = make_float4(x1, y1, x2, y2);
        g_ta [pos]  = (x2 - x1) * (y2 - y1);
    }

    // ---------------- Grid barrier (13 blocks, all co-resident) -------------
    __threadfence();
    __syncthreads();
    if (tid == 0) atomicAdd(&g_done1, 1);
    if (tid == 0) {
        volatile int* vd = &g_done1;
        while (*vd < nblocks) { }
    }
    __syncthreads();
    __threadfence();

    const int K = g_cnt;

    // ---------------- Phase 2: owning warp computes conf loss ---------------
    // pred box already in registers; warp cooperates per obj lane.
    unsigned obj_mask = __ballot_sync(0xffffffffu, isObj);
    while (obj_mask) {
        int src = __ffs(obj_mask) - 1;
        obj_mask &= obj_mask - 1;
        float bx1 = __shfl_sync(0xffffffffu, px1, src);
        float by1 = __shfl_sync(0xffffffffu, py1, src);
        float bx2 = __shfl_sync(0xffffffffu, px2, src);
        float by2 = __shfl_sync(0xffffffffu, py2, src);
        float ba  = __shfl_sync(0xffffffffu, pa,  src);
        float best = -1.0f;
        for (int j = lane; j < K; j += 32) {
            float4 tb = g_tbox[j];
            float iw = fminf(bx2, tb.z) - fmaxf(bx1, tb.x);
            float ih = fminf(by2, tb.w) - fmaxf(by1, tb.y);
            iw = fmaxf(iw, 0.0f);
            ih = fmaxf(ih, 0.0f);
            float inter = iw * ih;
            float iou = __fdividef(inter, ba + g_ta[j] - inter + EPS_IOU);
            best = fmaxf(best, iou);
        }
        #pragma unroll
        for (int off = 16; off > 0; off >>= 1)
            best = fmaxf(best, __shfl_xor_sync(0xffffffffu, best, off));
        if (lane == src) {
            float d = pc - best;
            local += d * d;
        }
    }

    // ---------------- Single merged block reduction (float) -----------------
    #pragma unroll
    for (int off = 16; off > 0; off >>= 1)
        local += __shfl_down_sync(0xffffffffu, local, off);
    if (lane == 0) swred[wid] = local;
    __syncthreads();
    if (wid == 0) {
        float v = (lane < NWARP) ? swred[lane] : 0.0f;
        #pragma unroll
        for (int off = 8; off > 0; off >>= 1)
            v += __shfl_down_sync(0xffffffffu, v, off);
        if (lane == 0) g_part[blockIdx.x] = (double)v;
    }

    // ---------------- Last block finalizes + resets --------------------------
    __threadfence();
    __syncthreads();
    __shared__ int is_last;
    if (tid == 0) is_last = (atomicAdd(&g_done2, 1) == nblocks - 1) ? 1 : 0;
    __syncthreads();
    if (!is_last) return;

    if (tid == 0) {
        double tot = 0.0;
        for (int b = 0; b < nblocks; b++) tot += g_part[b];
        out[0] = (float)(tot * (double)invB);
        g_cnt   = 0;   // reset for next graph replay
        g_done1 = 0;
        g_done2 = 0;
    }
}

extern "C" void kernel_launch(void* const* d_in, const int* in_sizes, int n_in,
                              void* d_out, int out_size) {
    const float* pred = (const float*)d_in[0];
    const float* targ = (const float*)d_in[1];
    float* out = (float*)d_out;

    int total = in_sizes[0];           // B * S * S * N
    int M = total / NCH;               // 6272 cells
    int B = M / (SS * SS);
    float invB = 1.0f / (float)B;

    int nblocks = (M + TPB - 1) / TPB; // 13  (co-resident: 13 << #SMs)
    k_yolo_v14<<<nblocks, TPB>>>(pred, targ, out, M, nblocks, invB);
}

// round 15
// speedup vs baseline: 1.5122x; 1.0379x over previous
#include <cuda_runtime.h>
#include <cuda_bf16.h>

#define SS 7
#define NCH 25
#define MAXCELLS 8192
#define LAMBDA_COORD 5.0f
#define LAMBDA_NOOBJ 0.5f
#define EPS_SQRT 1e-6f
#define EPS_IOU 1e-10f
#define TPB 512
#define NWARP (TPB / 32)
#define MAXBLK 64

// __device__ globals (zero-init; kernel self-resets -> identical on every replay)
__device__ double g_part[MAXBLK];
__device__ int    g_cnt   = 0;
__device__ int    g_done1 = 0;
__device__ int    g_done2 = 0;
// compacted object-target boxes: corners packed as float4 (area recomputed)
__device__ float4 g_tbox[MAXCELLS];

__global__ void __launch_bounds__(TPB)
k_yolo_v15(const float* __restrict__ pred,
           const float* __restrict__ targ,
           float* __restrict__ out,
           int M, int nblocks, float invB) {
    const int tid  = threadIdx.x;
    const int lane = tid & 31;
    const int wid  = tid >> 5;
    const int i    = blockIdx.x * TPB + tid;   // owned cell

    __shared__ int   s_wbase[NWARP];
    __shared__ int   s_cnt, s_gbase;
    __shared__ float swred[NWARP];
    if (tid == 0) s_cnt = 0;
    __syncthreads();

    // ---------------- Phase 1: own-cell losses + target compaction ----------
    float local = 0.0f;
    bool isObj = false;
    float px1=0.f, py1=0.f, px2=0.f, py2=0.f, pa=0.f, pc=0.f;

    if (i < M) {
        const float* pp = pred + (size_t)i * NCH;
        const float* tt = targ + (size_t)i * NCH;
        // two independent loads, one memory latency
        float t4 = __ldg(&tt[4]);
        pc = __ldg(&pp[4]);
        if (t4 > 0.0f) {
            isObj = true;
            float p0 = pp[0], p1 = pp[1], p2 = pp[2], p3 = pp[3];
            float t0 = tt[0], t1 = tt[1], t2 = tt[2], t3 = tt[3];
            float dx = p0 - t0;
            float dy = p1 - t1;
            float sw = sqrtf(p2 + EPS_SQRT) - sqrtf(t2 + EPS_SQRT);
            float sh = sqrtf(p3 + EPS_SQRT) - sqrtf(t3 + EPS_SQRT);
            float cl = 0.0f;
            #pragma unroll
            for (int c = 5; c < NCH; c++) {
                float d = pp[c] - tt[c];
                cl += d * d;
            }
            local += LAMBDA_COORD * (dx*dx + dy*dy + sw*sw + sh*sh) + cl;
            // pred box stays in registers for phase 2
            px1 = p0 - p2*0.5f;  py1 = p1 - p3*0.5f;
            px2 = p0 + p2*0.5f;  py2 = p1 + p3*0.5f;
            pa  = (px2 - px1) * (py2 - py1);
        } else {
            local += LAMBDA_NOOBJ * pc * pc;
        }
    }

    // warp -> block -> one global atomic for compaction offsets
    unsigned m = __ballot_sync(0xffffffffu, isObj);
    int nobj = __popc(m);
    if (lane == 0) s_wbase[wid] = (nobj > 0) ? atomicAdd(&s_cnt, nobj) : 0;
    __syncthreads();
    if (tid == 0) s_gbase = (s_cnt > 0) ? atomicAdd(&g_cnt, s_cnt) : 0;
    __syncthreads();
    if (isObj) {
        int pos = s_gbase + s_wbase[wid] + __popc(m & ((1u << lane) - 1));
        const float* tt = targ + (size_t)i * NCH;   // L1/L2 hot after phase 1
        float t0 = tt[0], t1 = tt[1], t2 = tt[2], t3 = tt[3];
        g_tbox[pos] = make_float4(t0 - t2*0.5f, t1 - t3*0.5f,
                                  t0 + t2*0.5f, t1 + t3*0.5f);
    }

    // ---------------- Grid barrier (13 blocks, all co-resident) -------------
    __threadfence();
    __syncthreads();
    if (tid == 0) {
        atomicAdd(&g_done1, 1);
        volatile int* vd = &g_done1;
        while (*vd < nblocks) { }
    }
    __syncthreads();
    __threadfence();

    const int K = g_cnt;

    // ---------------- Phase 2: owning warp computes conf loss ---------------
    unsigned obj_mask = __ballot_sync(0xffffffffu, isObj);
    while (obj_mask) {
        int src = __ffs(obj_mask) - 1;
        obj_mask &= obj_mask - 1;
        float bx1 = __shfl_sync(0xffffffffu, px1, src);
        float by1 = __shfl_sync(0xffffffffu, py1, src);
        float bx2 = __shfl_sync(0xffffffffu, px2, src);
        float by2 = __shfl_sync(0xffffffffu, py2, src);
        float ba  = __shfl_sync(0xffffffffu, pa,  src);
        float best = -1.0f;
        for (int j = lane; j < K; j += 32) {
            float4 tb = g_tbox[j];
            float iw = fminf(bx2, tb.z) - fmaxf(bx1, tb.x);
            float ih = fminf(by2, tb.w) - fmaxf(by1, tb.y);
            iw = fmaxf(iw, 0.0f);
            ih = fmaxf(ih, 0.0f);
            float inter = iw * ih;
            float tarea = (tb.z - tb.x) * (tb.w - tb.y);   // 2 FMAs, no load
            float iou = __fdividef(inter, ba + tarea - inter + EPS_IOU);
            best = fmaxf(best, iou);
        }
        #pragma unroll
        for (int off = 16; off > 0; off >>= 1)
            best = fmaxf(best, __shfl_xor_sync(0xffffffffu, best, off));
        if (lane == src) {
            float d = pc - best;
            local += d * d;
        }
    }

    // ---------------- Single merged block reduction (float) -----------------
    #pragma unroll
    for (int off = 16; off > 0; off >>= 1)
        local += __shfl_down_sync(0xffffffffu, local, off);
    if (lane == 0) swred[wid] = local;
    __syncthreads();
    if (wid == 0) {
        float v = (lane < NWARP) ? swred[lane] : 0.0f;
        #pragma unroll
        for (int off = 8; off > 0; off >>= 1)
            v += __shfl_down_sync(0xffffffffu, v, off);
        if (lane == 0) g_part[blockIdx.x] = (double)v;
    }

    // ---------------- Last block finalizes + resets --------------------------
    __threadfence();
    __syncthreads();
    __shared__ int is_last;
    if (tid == 0) is_last = (atomicAdd(&g_done2, 1) == nblocks - 1) ? 1 : 0;
    __syncthreads();
    if (!is_last) return;

    if (tid == 0) {
        double tot = 0.0;
        for (int b = 0; b < nblocks; b++) tot += g_part[b];
        out[0] = (float)(tot * (double)invB);
        g_cnt   = 0;   // reset for next graph replay
        g_done1 = 0;
        g_done2 = 0;
    }
}

extern "C" void kernel_launch(void* const* d_in, const int* in_sizes, int n_in,
                              void* d_out, int out_size) {
    const float* pred = (const float*)d_in[0];
    const float* targ = (const float*)d_in[1];
    float* out = (float*)d_out;

    int total = in_sizes[0];           // B * S * S * N
    int M = total / NCH;               // 6272 cells
    int B = M / (SS * SS);
    float invB = 1.0f / (float)B;

    int nblocks = (M + TPB - 1) / TPB; // 13  (co-resident: 13 << #SMs)
    k_yolo_v15<<<nblocks, TPB>>>(pred, targ, out, M, nblocks, invB);
}